// round 8
// baseline (speedup 1.0000x reference)
#include <cuda_runtime.h>
#include <math.h>

// Problem constants
#define BATCH 4
#define SEQ   2048
#define EMBD  1024
#define NH    16
#define DKH   64
#define BH    (BATCH * NH)      // 64
#define BSQ   (BATCH * SEQ)     // 8192

#define QKV_ELEMS  (BATCH * NH * SEQ * DKH)          // 8,388,608
#define PRED_ELEMS (BSQ * EMBD)                      // 8,388,608
#define ATTN_ELEMS ((size_t)BH * SEQ * SEQ)          // 268,435,456

// Scratch (allocation-free: device globals)
__device__ float g_q[QKV_ELEMS];        // [B,H,S,D]
__device__ float g_k[QKV_ELEMS];        // [B,H,S,D]
__device__ float g_v[QKV_ELEMS];        // [B,H,S,D]
__device__ float g_pred[PRED_ELEMS];    // [B,S,H*D]
__device__ float g_attn_fb[ATTN_ELEMS]; // fallback attn scratch [B,H,S,S]
__device__ int   g_mask_mode;           // 0=uint8, 1=int32, 2=float32

// ---------------------------------------------------------------------------
// Kernel 0: detect mask element dtype from its bit patterns.
// int32 bool: every 32-bit word is 0 or 1.
// float32 bool: every word is 0 or 0x3f800000.
// uint8 bool: words contain ones in arbitrary byte lanes (10% density ->
//             certainty within the first 256KB scanned).
// Deterministic, graph-capturable, ~5us.
// ---------------------------------------------------------------------------
__global__ void detect_mask_kernel(const unsigned int* __restrict__ m)
{
    __shared__ int s01, sf;
    if (threadIdx.x == 0) { s01 = 1; sf = 1; }
    __syncthreads();
    int a01 = 1, af = 1;
    for (int i = threadIdx.x; i < 65536; i += blockDim.x) {
        const unsigned int w = m[i];
        if (w > 1u) a01 = 0;
        if (w != 0u && w != 0x3f800000u) af = 0;
    }
    if (!a01) atomicAnd(&s01, 0);
    if (!af)  atomicAnd(&sf, 0);
    __syncthreads();
    if (threadIdx.x == 0) g_mask_mode = s01 ? 1 : (sf ? 2 : 0);
}

// ---------------------------------------------------------------------------
// Kernel 1: fused QKV projection.  z selects (Q,W_Q)->g_q etc.
// GEMM M=8192, N=1024, K=1024, output scattered to [B,H,S,D].
// 64x64 block tile, 256 threads, 4x4 per thread, k-step 16.
// ---------------------------------------------------------------------------
__global__ __launch_bounds__(256) void proj_kernel(
    const float* __restrict__ Qin, const float* __restrict__ Kin,
    const float* __restrict__ Vin,
    const float* __restrict__ WQ, const float* __restrict__ WK,
    const float* __restrict__ WV)
{
    const float* A; const float* W; float* O;
    if (blockIdx.z == 0)      { A = Qin; W = WQ; O = g_q; }
    else if (blockIdx.z == 1) { A = Kin; W = WK; O = g_k; }
    else                      { A = Vin; W = WV; O = g_v; }

    __shared__ float As[16][68];   // As[k][m]
    __shared__ float Bs[16][68];   // Bs[k][n]

    const int tid = threadIdx.x;
    const int tx = tid & 15, ty = tid >> 4;
    const int m0 = blockIdx.y * 64, n0 = blockIdx.x * 64;
    const int arow = tid >> 2,  acol = (tid & 3) * 4;
    const int brow = tid >> 4,  bcol = (tid & 15) * 4;

    float acc[4][4] = {};

    for (int kt = 0; kt < EMBD; kt += 16) {
        float4 av = *(const float4*)&A[(size_t)(m0 + arow) * EMBD + kt + acol];
        As[acol + 0][arow] = av.x;
        As[acol + 1][arow] = av.y;
        As[acol + 2][arow] = av.z;
        As[acol + 3][arow] = av.w;
        float4 bv = *(const float4*)&W[(size_t)(kt + brow) * EMBD + n0 + bcol];
        *(float4*)&Bs[brow][bcol] = bv;
        __syncthreads();
        #pragma unroll
        for (int kk = 0; kk < 16; ++kk) {
            const float4 a = *(const float4*)&As[kk][ty * 4];
            const float4 b = *(const float4*)&Bs[kk][tx * 4];
            const float ar[4] = {a.x, a.y, a.z, a.w};
            const float br[4] = {b.x, b.y, b.z, b.w};
            #pragma unroll
            for (int i = 0; i < 4; ++i)
                #pragma unroll
                for (int j = 0; j < 4; ++j)
                    acc[i][j] = fmaf(ar[i], br[j], acc[i][j]);
        }
        __syncthreads();
    }

    #pragma unroll
    for (int i = 0; i < 4; ++i) {
        const int m = m0 + ty * 4 + i;
        const int b = m >> 11, s = m & (SEQ - 1);
        #pragma unroll
        for (int j = 0; j < 4; ++j) {
            const int n = n0 + tx * 4 + j;
            const int h = n >> 6, d = n & (DKH - 1);
            O[(((size_t)(b * NH + h)) * SEQ + s) * DKH + d] = acc[i][j];
        }
    }
}

// ---------------------------------------------------------------------------
// Kernel 2: masked scores.  Per (b,h): S[sq,sk] = (q.k)/8, masked -> -1e9.
// GEMM M=N=2048, K=64. B operand (K matrix) loaded transposed.
// Mask dtype resolved at runtime via g_mask_mode (epilogue only).
// ---------------------------------------------------------------------------
__global__ __launch_bounds__(256) void scores_kernel(
    const void* __restrict__ mask, float* __restrict__ attn)
{
    const int z = blockIdx.z;          // b*NH + h
    const int b = z >> 4;
    const float* qb = g_q + (size_t)z * SEQ * DKH;
    const float* kb = g_k + (size_t)z * SEQ * DKH;

    __shared__ float As[16][68];   // As[d][sq]
    __shared__ float Bs[16][68];   // Bs[d][sk]

    const int tid = threadIdx.x;
    const int tx = tid & 15, ty = tid >> 4;
    const int m0 = blockIdx.y * 64, n0 = blockIdx.x * 64;
    const int row = tid >> 2, col = (tid & 3) * 4;

    float acc[4][4] = {};

    for (int kt = 0; kt < DKH; kt += 16) {
        float4 av = *(const float4*)&qb[(size_t)(m0 + row) * DKH + kt + col];
        As[col + 0][row] = av.x;
        As[col + 1][row] = av.y;
        As[col + 2][row] = av.z;
        As[col + 3][row] = av.w;
        float4 bv = *(const float4*)&kb[(size_t)(n0 + row) * DKH + kt + col];
        Bs[col + 0][row] = bv.x;
        Bs[col + 1][row] = bv.y;
        Bs[col + 2][row] = bv.z;
        Bs[col + 3][row] = bv.w;
        __syncthreads();
        #pragma unroll
        for (int kk = 0; kk < 16; ++kk) {
            const float4 a = *(const float4*)&As[kk][ty * 4];
            const float4 bq = *(const float4*)&Bs[kk][tx * 4];
            const float ar[4] = {a.x, a.y, a.z, a.w};
            const float br[4] = {bq.x, bq.y, bq.z, bq.w};
            #pragma unroll
            for (int i = 0; i < 4; ++i)
                #pragma unroll
                for (int j = 0; j < 4; ++j)
                    acc[i][j] = fmaf(ar[i], br[j], acc[i][j]);
        }
        __syncthreads();
    }

    const int mode = g_mask_mode;
    const unsigned char* m8  = (const unsigned char*)mask;
    const int*           m32 = (const int*)mask;
    const float*         mf  = (const float*)mask;

    #pragma unroll
    for (int i = 0; i < 4; ++i) {
        const int m = m0 + ty * 4 + i;
        const size_t mbase = ((size_t)b * SEQ + m) * SEQ;
        float* orow = attn + (((size_t)z * SEQ) + m) * SEQ;
        #pragma unroll
        for (int j = 0; j < 4; ++j) {
            const int n = n0 + tx * 4 + j;
            float v = acc[i][j] * 0.125f;          // 1/sqrt(64)
            bool masked;
            if (mode == 1)      masked = (m32[mbase + n] != 0);
            else if (mode == 2) masked = (mf[mbase + n] != 0.0f);
            else                masked = (m8[mbase + n] != 0);
            if (masked) v = -1e9f;
            orow[n] = v;
        }
    }
}

// ---------------------------------------------------------------------------
// Kernel 3: row softmax over 2048 keys.  One block (256 thr) per row.
// Row held entirely in registers (8 floats/thread): 1 read + 1 write pass.
// ---------------------------------------------------------------------------
__global__ __launch_bounds__(256) void softmax_kernel(float* __restrict__ attn)
{
    float* p = attn + (size_t)blockIdx.x * SEQ;
    const int t = threadIdx.x;

    float v[8];
    float m = -3.4e38f;
    #pragma unroll
    for (int j = 0; j < 8; ++j) {
        v[j] = p[t + j * 256];
        m = fmaxf(m, v[j]);
    }

    __shared__ float red[8];
    __shared__ float bmax, bsum;
    #pragma unroll
    for (int o = 16; o > 0; o >>= 1) m = fmaxf(m, __shfl_xor_sync(0xffffffffu, m, o));
    if ((t & 31) == 0) red[t >> 5] = m;
    __syncthreads();
    if (t == 0) {
        float mm = red[0];
        #pragma unroll
        for (int i = 1; i < 8; ++i) mm = fmaxf(mm, red[i]);
        bmax = mm;
    }
    __syncthreads();
    m = bmax;

    float s = 0.f;
    #pragma unroll
    for (int j = 0; j < 8; ++j) {
        v[j] = __expf(v[j] - m);
        s += v[j];
    }
    __syncthreads();   // protect red[] reuse
    #pragma unroll
    for (int o = 16; o > 0; o >>= 1) s += __shfl_xor_sync(0xffffffffu, s, o);
    if ((t & 31) == 0) red[t >> 5] = s;
    __syncthreads();
    if (t == 0) {
        float ss = red[0];
        #pragma unroll
        for (int i = 1; i < 8; ++i) ss += red[i];
        bsum = ss;
    }
    __syncthreads();
    const float inv = 1.0f / bsum;

    #pragma unroll
    for (int j = 0; j < 8; ++j) p[t + j * 256] = v[j] * inv;
}

// ---------------------------------------------------------------------------
// Kernel 4: pred = attn @ v.  Per (b,h): M=2048, N=64, K=2048.
// Output scattered to [B,S,H*D] layout for the FC GEMM.
// ---------------------------------------------------------------------------
__global__ __launch_bounds__(256) void av_kernel(const float* __restrict__ attn)
{
    const int z = blockIdx.z;          // b*NH + h
    const int b = z >> 4, h = z & 15;
    const float* Ab = attn + (size_t)z * SEQ * SEQ;
    const float* Vb = g_v + (size_t)z * SEQ * DKH;

    __shared__ float As[16][68];
    __shared__ float Bs[16][68];

    const int tid = threadIdx.x;
    const int tx = tid & 15, ty = tid >> 4;
    const int m0 = blockIdx.y * 64;
    const int arow = tid >> 2, acol = (tid & 3) * 4;
    const int brow = tid >> 4, bcol = (tid & 15) * 4;

    float acc[4][4] = {};

    for (int kt = 0; kt < SEQ; kt += 16) {
        float4 av = *(const float4*)&Ab[(size_t)(m0 + arow) * SEQ + kt + acol];
        As[acol + 0][arow] = av.x;
        As[acol + 1][arow] = av.y;
        As[acol + 2][arow] = av.z;
        As[acol + 3][arow] = av.w;
        float4 bv = *(const float4*)&Vb[(size_t)(kt + brow) * DKH + bcol];
        *(float4*)&Bs[brow][bcol] = bv;
        __syncthreads();
        #pragma unroll
        for (int kk = 0; kk < 16; ++kk) {
            const float4 a = *(const float4*)&As[kk][ty * 4];
            const float4 bq = *(const float4*)&Bs[kk][tx * 4];
            const float ar[4] = {a.x, a.y, a.z, a.w};
            const float br[4] = {bq.x, bq.y, bq.z, bq.w};
            #pragma unroll
            for (int i = 0; i < 4; ++i)
                #pragma unroll
                for (int j = 0; j < 4; ++j)
                    acc[i][j] = fmaf(ar[i], br[j], acc[i][j]);
        }
        __syncthreads();
    }

    #pragma unroll
    for (int i = 0; i < 4; ++i) {
        const int m = m0 + ty * 4 + i;
        #pragma unroll
        for (int j = 0; j < 4; ++j) {
            const int n = tx * 4 + j;
            g_pred[((size_t)(b * SEQ + m)) * EMBD + h * DKH + n] = acc[i][j];
        }
    }
}

// ---------------------------------------------------------------------------
// Kernel 5: out = pred @ W_fc.  M=8192, N=1024, K=1024.
// ---------------------------------------------------------------------------
__global__ __launch_bounds__(256) void fc_kernel(
    const float* __restrict__ Wfc, float* __restrict__ out)
{
    __shared__ float As[16][68];
    __shared__ float Bs[16][68];

    const int tid = threadIdx.x;
    const int tx = tid & 15, ty = tid >> 4;
    const int m0 = blockIdx.y * 64, n0 = blockIdx.x * 64;
    const int arow = tid >> 2, acol = (tid & 3) * 4;
    const int brow = tid >> 4, bcol = (tid & 15) * 4;

    float acc[4][4] = {};

    for (int kt = 0; kt < EMBD; kt += 16) {
        float4 av = *(const float4*)&g_pred[(size_t)(m0 + arow) * EMBD + kt + acol];
        As[acol + 0][arow] = av.x;
        As[acol + 1][arow] = av.y;
        As[acol + 2][arow] = av.z;
        As[acol + 3][arow] = av.w;
        float4 bv = *(const float4*)&Wfc[(size_t)(kt + brow) * EMBD + n0 + bcol];
        *(float4*)&Bs[brow][bcol] = bv;
        __syncthreads();
        #pragma unroll
        for (int kk = 0; kk < 16; ++kk) {
            const float4 a = *(const float4*)&As[kk][ty * 4];
            const float4 bq = *(const float4*)&Bs[kk][tx * 4];
            const float ar[4] = {a.x, a.y, a.z, a.w};
            const float br[4] = {bq.x, bq.y, bq.z, bq.w};
            #pragma unroll
            for (int i = 0; i < 4; ++i)
                #pragma unroll
                for (int j = 0; j < 4; ++j)
                    acc[i][j] = fmaf(ar[i], br[j], acc[i][j]);
        }
        __syncthreads();
    }

    #pragma unroll
    for (int i = 0; i < 4; ++i) {
        const int m = m0 + ty * 4 + i;
        #pragma unroll
        for (int j = 0; j < 4; ++j) {
            const int n = n0 + tx * 4 + j;
            out[(size_t)m * EMBD + n] = acc[i][j];
        }
    }
}

// ---------------------------------------------------------------------------
extern "C" void kernel_launch(void* const* d_in, const int* in_sizes, int n_in,
                              void* d_out, int out_size)
{
    const float* Q  = (const float*)d_in[0];
    const float* K  = (const float*)d_in[1];
    const float* V  = (const float*)d_in[2];
    const void*  mask = d_in[3];
    const float* WQ  = (const float*)d_in[4];
    const float* WK  = (const float*)d_in[5];
    const float* WV  = (const float*)d_in[6];
    const float* Wfc = (const float*)d_in[7];
    float* out = (float*)d_out;

    // attn target: second tuple element of the reference output if the harness
    // expects it, otherwise device-global scratch.
    float* attn_ptr;
    if (out_size >= (int)(PRED_ELEMS + ATTN_ELEMS)) {
        attn_ptr = out + PRED_ELEMS;
    } else {
        void* p = nullptr;
        cudaGetSymbolAddress(&p, g_attn_fb);
        attn_ptr = (float*)p;
    }

    detect_mask_kernel<<<1, 1024>>>((const unsigned int*)mask);
    proj_kernel<<<dim3(EMBD / 64, BSQ / 64, 3), 256>>>(Q, K, V, WQ, WK, WV);
    scores_kernel<<<dim3(SEQ / 64, SEQ / 64, BH), 256>>>(mask, attn_ptr);
    softmax_kernel<<<BH * SEQ, 256>>>(attn_ptr);
    av_kernel<<<dim3(1, SEQ / 64, BH), 256>>>(attn_ptr);
    fc_kernel<<<dim3(EMBD / 64, BSQ / 64, 1), 256>>>(Wfc, out);
}

// round 11
// speedup vs baseline: 1.4063x; 1.4063x over previous
#include <cuda_runtime.h>
#include <cuda_bf16.h>
#include <stdint.h>

#define BATCH 4
#define SEQ   2048
#define EMBD  1024
#define NH    16
#define DKH   64
#define BH    64
#define BSQ   8192
#define QKV_ELEMS  (BATCH * NH * SEQ * DKH)
#define PRED_ELEMS (BSQ * EMBD)
#define ATTN_ELEMS ((size_t)BH * SEQ * SEQ)

__device__ float  g_attn_fb[ATTN_ELEMS];
__device__ int    g_mask_mode;
__device__ float2 g_rstat[BH * SEQ];                 // {rowmax, 1/rowsum}
__device__ __nv_bfloat16 g_inh[3u * QKV_ELEMS], g_inl[3u * QKV_ELEMS];
__device__ __nv_bfloat16 g_wth[4u * EMBD * EMBD], g_wtl[4u * EMBD * EMBD]; // W^T [N,K]
__device__ __nv_bfloat16 g_qh[QKV_ELEMS], g_ql[QKV_ELEMS];   // [B,H,S,D]
__device__ __nv_bfloat16 g_kh[QKV_ELEMS], g_kl[QKV_ELEMS];
__device__ __nv_bfloat16 g_vh[QKV_ELEMS], g_vl[QKV_ELEMS];
__device__ __nv_bfloat16 g_ph[PRED_ELEMS], g_pl[PRED_ELEMS]; // [B,S,H*D]

#define OF_AH  1024u
#define OF_AL  (1024u + 16384u)
#define OF_BH  (1024u + 32768u)
#define OF_BL  (1024u + 49152u)
#define SMEM_BYTES (1024 + 4 * 16384)

__device__ __forceinline__ uint32_t smem_u32(const void* p) {
    uint32_t a;
    asm("{ .reg .u64 t; cvta.to.shared.u64 t, %1; cvt.u32.u64 %0, t; }" : "=r"(a) : "l"(p));
    return a;
}
__device__ __forceinline__ void split_bf(float x, __nv_bfloat16& h, __nv_bfloat16& l) {
    h = __float2bfloat16(x);
    l = __float2bfloat16(x - __bfloat162float(h));
}
__device__ __forceinline__ uint32_t pack2(__nv_bfloat16 a, __nv_bfloat16 b) {
    return (uint32_t)__bfloat16_as_ushort(a) | ((uint32_t)__bfloat16_as_ushort(b) << 16);
}
__device__ __forceinline__ void mma16816(float* d, const uint32_t* a, uint32_t b0, uint32_t b1) {
    asm volatile("mma.sync.aligned.m16n8k16.row.col.f32.bf16.bf16.f32 "
                 "{%0,%1,%2,%3}, {%4,%5,%6,%7}, {%8,%9}, {%0,%1,%2,%3};"
                 : "+f"(d[0]), "+f"(d[1]), "+f"(d[2]), "+f"(d[3])
                 : "r"(a[0]), "r"(a[1]), "r"(a[2]), "r"(a[3]), "r"(b0), "r"(b1));
}
__device__ __forceinline__ void ldsm4(uint32_t* r, uint32_t a) {
    asm volatile("ldmatrix.sync.aligned.m8n8.x4.shared.b16 {%0,%1,%2,%3}, [%4];"
                 : "=r"(r[0]), "=r"(r[1]), "=r"(r[2]), "=r"(r[3]) : "r"(a));
}
__device__ __forceinline__ void ldsm4t(uint32_t* r, uint32_t a) {
    asm volatile("ldmatrix.sync.aligned.m8n8.x4.trans.shared.b16 {%0,%1,%2,%3}, [%4];"
                 : "=r"(r[0]), "=r"(r[1]), "=r"(r[2]), "=r"(r[3]) : "r"(a));
}

// [rows x 64] bf16 K-major -> swizzled SMEM (chunk ^= row&7), 16B granules.
__device__ __forceinline__ void ld_tile(const __nv_bfloat16* __restrict__ s, int ld, int rows,
                                        unsigned char* d, int tid) {
    for (int i = tid; i < rows * 8; i += 256) {
        const int r = i >> 3, c = i & 7;
        const uint4 w = *(const uint4*)(s + (size_t)r * ld + c * 8);
        *(uint4*)(d + r * 128 + ((c ^ (r & 7)) << 4)) = w;
    }
}
// [128 x 64] f32 -> hi/lo swizzled SMEM, optional fused exp((x-m)*inv).
__device__ __forceinline__ void ld_tile_att(const float* __restrict__ s, int ld,
                                            unsigned char* dh, unsigned char* dl,
                                            const float2* st, int fused, int tid) {
    for (int i = tid; i < 128 * 16; i += 256) {
        const int r = i >> 4, q = i & 15;
        float4 v = *(const float4*)(s + (size_t)r * ld + q * 4);
        if (fused) {
            const float2 w = st[r];
            v.x = __expf(v.x - w.x) * w.y; v.y = __expf(v.y - w.x) * w.y;
            v.z = __expf(v.z - w.x) * w.y; v.w = __expf(v.w - w.x) * w.y;
        }
        __nv_bfloat16 h0, h1, h2, h3, l0, l1, l2, l3;
        split_bf(v.x, h0, l0); split_bf(v.y, h1, l1);
        split_bf(v.z, h2, l2); split_bf(v.w, h3, l3);
        const uint32_t o = r * 128 + q * 8, sw = o ^ ((o >> 3) & 0x70);
        *(uint2*)(dh + sw) = make_uint2(pack2(h0, h1), pack2(h2, h3));
        *(uint2*)(dl + sw) = make_uint2(pack2(l0, l1), pack2(l2, l3));
    }
}

// One K=64 chunk, 3 split passes. Warps 4x2 (M x N), warp tile 32 x NB/2.
template<int NB, bool TRB>
__device__ __forceinline__ void hmma_chunk(uint32_t sb, int wid, int lane, float* acc) {
    constexpr int NA = NB / 16;                      // n-atoms per warp
    const int wm = (wid >> 1) * 32, wn = (wid & 1) * (NB / 2);
    const int l15 = lane & 15, lh = lane >> 4;
    #pragma unroll
    for (int p = 0; p < 3; ++p) {
        const uint32_t ab = sb + ((p == 2) ? OF_AL : OF_AH);
        const uint32_t bb = sb + ((p == 1) ? OF_BL : OF_BH);
        #pragma unroll
        for (int kk = 0; kk < 4; ++kk) {
            uint32_t af[2][4];
            #pragma unroll
            for (int im = 0; im < 2; ++im) {
                const int r = wm + im * 16 + l15, c = kk * 2 + lh;
                ldsm4(af[im], ab + r * 128 + ((c ^ (r & 7)) << 4));
            }
            #pragma unroll
            for (int ap = 0; ap < NA / 2; ++ap) {
                uint32_t bf[4];
                if (!TRB) {      // B tile [n][k]: {b0a0,b0a1,b1a0,b1a1}
                    const int r = wn + ap * 16 + l15, c = kk * 2 + lh;
                    ldsm4(bf, bb + r * 128 + ((c ^ (r & 7)) << 4));
                    #pragma unroll
                    for (int im = 0; im < 2; ++im) {
                        mma16816(acc + (im * NA + ap * 2) * 4,     af[im], bf[0], bf[2]);
                        mma16816(acc + (im * NA + ap * 2 + 1) * 4, af[im], bf[1], bf[3]);
                    }
                } else {         // B tile [k][n] via trans: {b0a0,b1a0,b0a1,b1a1}
                    const int r = kk * 16 + l15, c = ((wn + ap * 16) >> 3) + lh;
                    ldsm4t(bf, bb + r * 128 + ((c ^ (r & 7)) << 4));
                    #pragma unroll
                    for (int im = 0; im < 2; ++im) {
                        mma16816(acc + (im * NA + ap * 2) * 4,     af[im], bf[0], bf[1]);
                        mma16816(acc + (im * NA + ap * 2 + 1) * 4, af[im], bf[2], bf[3]);
                    }
                }
            }
        }
    }
}

__global__ void detect_mask_kernel(const unsigned int* __restrict__ m) {
    __shared__ int s01, sf;
    if (threadIdx.x == 0) { s01 = 1; sf = 1; }
    __syncthreads();
    int a01 = 1, af = 1;
    for (int i = threadIdx.x; i < 65536; i += blockDim.x) {
        const unsigned int w = m[i];
        if (w > 1u) a01 = 0;
        if (w != 0u && w != 0x3f800000u) af = 0;
    }
    if (!a01) atomicAnd(&s01, 0);
    if (!af)  atomicAnd(&sf, 0);
    __syncthreads();
    if (threadIdx.x == 0) g_mask_mode = s01 ? 1 : (sf ? 2 : 0);
}

__global__ __launch_bounds__(256) void convert_in_kernel(
    const float* __restrict__ Q, const float* __restrict__ K, const float* __restrict__ V) {
    const int z = blockIdx.z;
    const float* s = (z == 0) ? Q : (z == 1) ? K : V;
    const size_t i = ((size_t)blockIdx.x * 256 + threadIdx.x) * 4;
    const float4 v = *(const float4*)(s + i);
    __nv_bfloat16 h0, h1, h2, h3, l0, l1, l2, l3;
    split_bf(v.x, h0, l0); split_bf(v.y, h1, l1); split_bf(v.z, h2, l2); split_bf(v.w, h3, l3);
    const size_t o = (size_t)z * QKV_ELEMS + i;
    *(uint2*)(g_inh + o) = make_uint2(pack2(h0, h1), pack2(h2, h3));
    *(uint2*)(g_inl + o) = make_uint2(pack2(l0, l1), pack2(l2, l3));
}

__global__ __launch_bounds__(256) void convert_w_kernel(
    const float* __restrict__ WQ, const float* __restrict__ WK,
    const float* __restrict__ WV, const float* __restrict__ Wfc) {
    const int z = blockIdx.z;
    const float* W = (z == 0) ? WQ : (z == 1) ? WK : (z == 2) ? WV : Wfc;
    __shared__ float t[32][33];
    const int tx = threadIdx.x & 31, ty = threadIdx.x >> 5;
    const int x0 = blockIdx.x * 32, y0 = blockIdx.y * 32;
    #pragma unroll
    for (int j = 0; j < 4; ++j)
        t[ty + j * 8][tx] = W[(size_t)(y0 + ty + j * 8) * EMBD + x0 + tx];
    __syncthreads();
    __nv_bfloat16* dh = g_wth + (size_t)z * EMBD * EMBD;
    __nv_bfloat16* dl = g_wtl + (size_t)z * EMBD * EMBD;
    #pragma unroll
    for (int j = 0; j < 4; ++j) {
        __nv_bfloat16 hh, ll;
        split_bf(t[tx][ty + j * 8], hh, ll);
        const size_t o = (size_t)(x0 + ty + j * 8) * EMBD + y0 + tx;
        dh[o] = hh; dl[o] = ll;
    }
}

// QKV projection: 128x128 tiles, 16 K64 chunks; scatter q/k/v -> [B,H,S,D] hi/lo.
__global__ __launch_bounds__(256, 2) void proj_gemm(void) {
    extern __shared__ unsigned char smem[];
    const uint32_t sb = smem_u32(smem);
    const int tid = threadIdx.x, wid = tid >> 5, lane = tid & 31;
    const int z = blockIdx.z, m0 = blockIdx.y * 128, n0 = blockIdx.x * 128;
    const __nv_bfloat16* Ah = g_inh + (size_t)z * QKV_ELEMS;
    const __nv_bfloat16* Al = g_inl + (size_t)z * QKV_ELEMS;
    const __nv_bfloat16* Bh = g_wth + (size_t)z * EMBD * EMBD;
    const __nv_bfloat16* Bl = g_wtl + (size_t)z * EMBD * EMBD;
    float acc[64] = {};
    for (int c = 0; c < 16; ++c) {
        __syncthreads();
        ld_tile(Ah + (size_t)m0 * EMBD + c * 64, EMBD, 128, smem + OF_AH, tid);
        ld_tile(Al + (size_t)m0 * EMBD + c * 64, EMBD, 128, smem + OF_AL, tid);
        ld_tile(Bh + (size_t)n0 * EMBD + c * 64, EMBD, 128, smem + OF_BH, tid);
        ld_tile(Bl + (size_t)n0 * EMBD + c * 64, EMBD, 128, smem + OF_BL, tid);
        __syncthreads();
        hmma_chunk<128, false>(sb, wid, lane, acc);
    }
    const int gid = lane >> 2, t4 = lane & 3, wm = (wid >> 1) * 32, wn = (wid & 1) * 64;
    __nv_bfloat16* dh = (z == 0) ? g_qh : (z == 1) ? g_kh : g_vh;
    __nv_bfloat16* dl = (z == 0) ? g_ql : (z == 1) ? g_kl : g_vl;
    #pragma unroll
    for (int im = 0; im < 2; ++im)
        #pragma unroll
        for (int ia = 0; ia < 8; ++ia) {
            const float* cc = acc + (im * 8 + ia) * 4;
            const int n = n0 + wn + ia * 8 + t4 * 2, h = n >> 6, d = n & 63;
            #pragma unroll
            for (int hr = 0; hr < 2; ++hr) {
                const int m = m0 + wm + im * 16 + gid + hr * 8;
                const int b = m >> 11, s = m & (SEQ - 1);
                __nv_bfloat16 p0, p1, q0, q1;
                split_bf(cc[hr * 2 + 0], p0, q0);
                split_bf(cc[hr * 2 + 1], p1, q1);
                const size_t o = (((size_t)(b * NH + h)) * SEQ + s) * DKH + d;
                *(uint32_t*)(dh + o) = pack2(p0, p1);
                *(uint32_t*)(dl + o) = pack2(q0, q1);
            }
        }
}

// scores: per (b,h) 128x128 tile, single K=64 chunk; masked raw scores out.
__global__ __launch_bounds__(256, 2) void scores_gemm(
    const void* __restrict__ mask, float* __restrict__ attn) {
    extern __shared__ unsigned char smem[];
    const uint32_t sb = smem_u32(smem);
    const int tid = threadIdx.x, wid = tid >> 5, lane = tid & 31;
    const int z = blockIdx.z, b = z >> 4;
    const int m0 = blockIdx.y * 128, n0 = blockIdx.x * 128;
    const size_t zo = (size_t)z * SEQ * DKH;
    ld_tile(g_qh + zo + (size_t)m0 * DKH, DKH, 128, smem + OF_AH, tid);
    ld_tile(g_ql + zo + (size_t)m0 * DKH, DKH, 128, smem + OF_AL, tid);
    ld_tile(g_kh + zo + (size_t)n0 * DKH, DKH, 128, smem + OF_BH, tid);
    ld_tile(g_kl + zo + (size_t)n0 * DKH, DKH, 128, smem + OF_BL, tid);
    __syncthreads();
    float acc[64] = {};
    hmma_chunk<128, false>(sb, wid, lane, acc);
    __syncthreads();                 // tiles dead; stage mask flags
    {
        const int mode = g_mask_mode;
        for (int i = tid; i < 128 * 32; i += 256) {
            const int r = i >> 5, c0 = (i & 31) * 4;
            const size_t g = ((size_t)b * SEQ + m0 + r) * SEQ + n0 + c0;
            uint32_t f4;
            if (mode == 1) {
                const int4 w = *(const int4*)((const int*)mask + g);
                f4 = (w.x?1u:0u) | ((w.y?1u:0u)<<8) | ((w.z?1u:0u)<<16) | ((w.w?1u:0u)<<24);
            } else if (mode == 2) {
                const float4 w = *(const float4*)((const float*)mask + g);
                f4 = (w.x!=0.f?1u:0u) | ((w.y!=0.f?1u:0u)<<8) | ((w.z!=0.f?1u:0u)<<16) | ((w.w!=0.f?1u:0u)<<24);
            } else {
                f4 = *(const uint32_t*)((const unsigned char*)mask + g);
            }
            *(uint32_t*)(smem + OF_AH + r * 132 + c0) = f4;
        }
    }
    __syncthreads();
    const int gid = lane >> 2, t4 = lane & 3, wm = (wid >> 1) * 32, wn = (wid & 1) * 64;
    #pragma unroll
    for (int im = 0; im < 2; ++im)
        #pragma unroll
        for (int ia = 0; ia < 8; ++ia) {
            const float* cc = acc + (im * 8 + ia) * 4;
            const int ln = wn + ia * 8 + t4 * 2;
            #pragma unroll
            for (int hr = 0; hr < 2; ++hr) {
                const int rl = wm + im * 16 + gid + hr * 8;
                const unsigned char* fr = smem + OF_AH + rl * 132 + ln;
                float2 o;
                o.x = fr[0] ? -1e9f : cc[hr * 2 + 0] * 0.125f;
                o.y = fr[1] ? -1e9f : cc[hr * 2 + 1] * 0.125f;
                *(float2*)(attn + ((size_t)z * SEQ + m0 + rl) * SEQ + n0 + ln) = o;
            }
        }
}

__global__ __launch_bounds__(256) void rowstats_kernel(const float* __restrict__ attn) {
    const float* p = attn + (size_t)blockIdx.x * SEQ;
    const int t = threadIdx.x;
    float v[8], m = -3.4e38f;
    #pragma unroll
    for (int j = 0; j < 8; ++j) { v[j] = p[t + j * 256]; m = fmaxf(m, v[j]); }
    __shared__ float red[8]; __shared__ float bmax;
    #pragma unroll
    for (int o = 16; o > 0; o >>= 1) m = fmaxf(m, __shfl_xor_sync(0xffffffffu, m, o));
    if ((t & 31) == 0) red[t >> 5] = m;
    __syncthreads();
    if (t == 0) {
        float mm = red[0];
        #pragma unroll
        for (int i = 1; i < 8; ++i) mm = fmaxf(mm, red[i]);
        bmax = mm;
    }
    __syncthreads();
    m = bmax;
    float s = 0.f;
    #pragma unroll
    for (int j = 0; j < 8; ++j) s += __expf(v[j] - m);
    __syncthreads();
    #pragma unroll
    for (int o = 16; o > 0; o >>= 1) s += __shfl_xor_sync(0xffffffffu, s, o);
    if ((t & 31) == 0) red[t >> 5] = s;
    __syncthreads();
    if (t == 0) {
        float ss = red[0];
        #pragma unroll
        for (int i = 1; i < 8; ++i) ss += red[i];
        g_rstat[blockIdx.x] = make_float2(m, 1.0f / ss);
    }
}

__global__ __launch_bounds__(256) void softmax_kernel(float* __restrict__ attn) {
    float* p = attn + (size_t)blockIdx.x * SEQ;
    const int t = threadIdx.x;
    float v[8], m = -3.4e38f;
    #pragma unroll
    for (int j = 0; j < 8; ++j) { v[j] = p[t + j * 256]; m = fmaxf(m, v[j]); }
    __shared__ float red[8]; __shared__ float bmax, bsum;
    #pragma unroll
    for (int o = 16; o > 0; o >>= 1) m = fmaxf(m, __shfl_xor_sync(0xffffffffu, m, o));
    if ((t & 31) == 0) red[t >> 5] = m;
    __syncthreads();
    if (t == 0) {
        float mm = red[0];
        #pragma unroll
        for (int i = 1; i < 8; ++i) mm = fmaxf(mm, red[i]);
        bmax = mm;
    }
    __syncthreads();
    m = bmax;
    float s = 0.f;
    #pragma unroll
    for (int j = 0; j < 8; ++j) { v[j] = __expf(v[j] - m); s += v[j]; }
    __syncthreads();
    #pragma unroll
    for (int o = 16; o > 0; o >>= 1) s += __shfl_xor_sync(0xffffffffu, s, o);
    if ((t & 31) == 0) red[t >> 5] = s;
    __syncthreads();
    if (t == 0) {
        float ss = red[0];
        #pragma unroll
        for (int i = 1; i < 8; ++i) ss += red[i];
        bsum = ss;
    }
    __syncthreads();
    const float inv = 1.0f / bsum;
    #pragma unroll
    for (int j = 0; j < 8; ++j) p[t + j * 256] = v[j] * inv;
}

// av: per (b,h) M=2048 N=64 K=2048; A=attn (optionally fused softmax), B=v via ldmatrix.trans.
__global__ __launch_bounds__(256, 2) void av_gemm(const float* __restrict__ attn, int fused) {
    extern __shared__ unsigned char smem[];
    const uint32_t sb = smem_u32(smem);
    const int tid = threadIdx.x, wid = tid >> 5, lane = tid & 31;
    const int z = blockIdx.z, b = z >> 4, h = z & 15, m0 = blockIdx.y * 128;
    const size_t zo = (size_t)z * SEQ * DKH;
    float2* st = (float2*)smem;
    if (fused && tid < 128) st[tid] = g_rstat[(size_t)z * SEQ + m0 + tid];
    float acc[32] = {};
    for (int c = 0; c < 32; ++c) {
        __syncthreads();
        ld_tile_att(attn + ((size_t)z * SEQ + m0) * SEQ + c * 64, SEQ,
                    smem + OF_AH, smem + OF_AL, st, fused, tid);
        ld_tile(g_vh + zo + (size_t)(c * 64) * DKH, DKH, 64, smem + OF_BH, tid);
        ld_tile(g_vl + zo + (size_t)(c * 64) * DKH, DKH, 64, smem + OF_BL, tid);
        __syncthreads();
        hmma_chunk<64, true>(sb, wid, lane, acc);
    }
    const int gid = lane >> 2, t4 = lane & 3, wm = (wid >> 1) * 32, wn = (wid & 1) * 32;
    #pragma unroll
    for (int im = 0; im < 2; ++im)
        #pragma unroll
        for (int ia = 0; ia < 4; ++ia) {
            const float* cc = acc + (im * 4 + ia) * 4;
            const int d = wn + ia * 8 + t4 * 2;
            #pragma unroll
            for (int hr = 0; hr < 2; ++hr) {
                const int m = m0 + wm + im * 16 + gid + hr * 8;
                __nv_bfloat16 p0, p1, q0, q1;
                split_bf(cc[hr * 2 + 0], p0, q0);
                split_bf(cc[hr * 2 + 1], p1, q1);
                const size_t o = ((size_t)(b * SEQ + m)) * EMBD + h * 64 + d;
                *(uint32_t*)(g_ph + o) = pack2(p0, p1);
                *(uint32_t*)(g_pl + o) = pack2(q0, q1);
            }
        }
}

// fc: out = pred @ Wfc, 128x128 tiles, 16 chunks, f32 output.
__global__ __launch_bounds__(256, 2) void fc_gemm(float* __restrict__ out) {
    extern __shared__ unsigned char smem[];
    const uint32_t sb = smem_u32(smem);
    const int tid = threadIdx.x, wid = tid >> 5, lane = tid & 31;
    const int m0 = blockIdx.y * 128, n0 = blockIdx.x * 128;
    const __nv_bfloat16* Bh = g_wth + (size_t)3 * EMBD * EMBD;
    const __nv_bfloat16* Bl = g_wtl + (size_t)3 * EMBD * EMBD;
    float acc[64] = {};
    for (int c = 0; c < 16; ++c) {
        __syncthreads();
        ld_tile(g_ph + (size_t)m0 * EMBD + c * 64, EMBD, 128, smem + OF_AH, tid);
        ld_tile(g_pl + (size_t)m0 * EMBD + c * 64, EMBD, 128, smem + OF_AL, tid);
        ld_tile(Bh + (size_t)n0 * EMBD + c * 64, EMBD, 128, smem + OF_BH, tid);
        ld_tile(Bl + (size_t)n0 * EMBD + c * 64, EMBD, 128, smem + OF_BL, tid);
        __syncthreads();
        hmma_chunk<128, false>(sb, wid, lane, acc);
    }
    const int gid = lane >> 2, t4 = lane & 3, wm = (wid >> 1) * 32, wn = (wid & 1) * 64;
    #pragma unroll
    for (int im = 0; im < 2; ++im)
        #pragma unroll
        for (int ia = 0; ia < 8; ++ia) {
            const float* cc = acc + (im * 8 + ia) * 4;
            const int n = n0 + wn + ia * 8 + t4 * 2;
            #pragma unroll
            for (int hr = 0; hr < 2; ++hr) {
                const int m = m0 + wm + im * 16 + gid + hr * 8;
                *(float2*)(out + (size_t)m * EMBD + n) =
                    make_float2(cc[hr * 2 + 0], cc[hr * 2 + 1]);
            }
        }
}

extern "C" void kernel_launch(void* const* d_in, const int* in_sizes, int n_in,
                              void* d_out, int out_size) {
    const float* Q = (const float*)d_in[0];
    const float* K = (const float*)d_in[1];
    const float* V = (const float*)d_in[2];
    const void* mask = d_in[3];
    const float* WQ = (const float*)d_in[4];
    const float* WK = (const float*)d_in[5];
    const float* WV = (const float*)d_in[6];
    const float* Wfc = (const float*)d_in[7];
    float* out = (float*)d_out;

    const int attn_out = (out_size >= (int)(PRED_ELEMS + ATTN_ELEMS));
    float* attn_ptr;
    if (attn_out) {
        attn_ptr = out + PRED_ELEMS;
    } else {
        void* p = nullptr;
        cudaGetSymbolAddress(&p, g_attn_fb);
        attn_ptr = (float*)p;
    }

    cudaFuncSetAttribute(proj_gemm,   cudaFuncAttributeMaxDynamicSharedMemorySize, SMEM_BYTES);
    cudaFuncSetAttribute(scores_gemm, cudaFuncAttributeMaxDynamicSharedMemorySize, SMEM_BYTES);
    cudaFuncSetAttribute(av_gemm,     cudaFuncAttributeMaxDynamicSharedMemorySize, SMEM_BYTES);
    cudaFuncSetAttribute(fc_gemm,     cudaFuncAttributeMaxDynamicSharedMemorySize, SMEM_BYTES);

    detect_mask_kernel<<<1, 1024>>>((const unsigned int*)mask);
    convert_in_kernel<<<dim3(QKV_ELEMS / 1024, 1, 3), 256>>>(Q, K, V);
    convert_w_kernel<<<dim3(32, 32, 4), 256>>>(WQ, WK, WV, Wfc);
    proj_gemm<<<dim3(8, 64, 3), 256, SMEM_BYTES>>>();
    scores_gemm<<<dim3(16, 16, BH), 256, SMEM_BYTES>>>(mask, attn_ptr);
    if (attn_out) {
        softmax_kernel<<<BH * SEQ, 256>>>(attn_ptr);
        av_gemm<<<dim3(1, 16, BH), 256, SMEM_BYTES>>>(attn_ptr, 0);
    } else {
        rowstats_kernel<<<BH * SEQ, 256>>>(attn_ptr);
        av_gemm<<<dim3(1, 16, BH), 256, SMEM_BYTES>>>(attn_ptr, 1);
    }
    fc_gemm<<<dim3(8, 64, 1), 256, SMEM_BYTES>>>(out);
}

// round 14
// speedup vs baseline: 2.4362x; 1.7323x over previous
#include <cuda_runtime.h>
#include <cuda_bf16.h>
#include <stdint.h>

#define BATCH 4
#define SEQ   2048
#define EMBD  1024
#define NH    16
#define DKH   64
#define BH    64
#define BSQ   8192
#define QKV_ELEMS  (BATCH * NH * SEQ * DKH)
#define PRED_ELEMS (BSQ * EMBD)
#define ATTN_ELEMS ((size_t)BH * SEQ * SEQ)

__device__ float  g_attn_fb[ATTN_ELEMS];
__device__ int    g_mask_mode;
__device__ float2 g_rstat[BH * SEQ];
__device__ __nv_bfloat16 g_inh[3u * QKV_ELEMS], g_inl[3u * QKV_ELEMS];
__device__ __nv_bfloat16 g_wth[4u * EMBD * EMBD], g_wtl[4u * EMBD * EMBD];
__device__ __nv_bfloat16 g_qh[QKV_ELEMS], g_ql[QKV_ELEMS];
__device__ __nv_bfloat16 g_kh[QKV_ELEMS], g_kl[QKV_ELEMS];
__device__ __nv_bfloat16 g_vh[QKV_ELEMS], g_vl[QKV_ELEMS];
__device__ __nv_bfloat16 g_ph[PRED_ELEMS], g_pl[PRED_ELEMS];

#define OF_AH  1024u
#define OF_AL  (1024u + 16384u)
#define OF_BH  (1024u + 32768u)
#define OF_BL  (1024u + 49152u)
#define SMEM_BYTES (1024 + 4 * 16384)

__device__ __forceinline__ uint32_t smem_u32(const void* p) {
    uint32_t a;
    asm("{ .reg .u64 t; cvta.to.shared.u64 t, %1; cvt.u32.u64 %0, t; }" : "=r"(a) : "l"(p));
    return a;
}
__device__ __forceinline__ void split_bf(float x, __nv_bfloat16& h, __nv_bfloat16& l) {
    h = __float2bfloat16(x);
    l = __float2bfloat16(x - __bfloat162float(h));
}
__device__ __forceinline__ uint32_t pack2(__nv_bfloat16 a, __nv_bfloat16 b) {
    return (uint32_t)__bfloat16_as_ushort(a) | ((uint32_t)__bfloat16_as_ushort(b) << 16);
}
__device__ __forceinline__ void mma16816(float* d, const uint32_t* a, uint32_t b0, uint32_t b1) {
    asm volatile("mma.sync.aligned.m16n8k16.row.col.f32.bf16.bf16.f32 "
                 "{%0,%1,%2,%3}, {%4,%5,%6,%7}, {%8,%9}, {%0,%1,%2,%3};"
                 : "+f"(d[0]), "+f"(d[1]), "+f"(d[2]), "+f"(d[3])
                 : "r"(a[0]), "r"(a[1]), "r"(a[2]), "r"(a[3]), "r"(b0), "r"(b1));
}
__device__ __forceinline__ void ldsm4(uint32_t* r, uint32_t a) {
    asm volatile("ldmatrix.sync.aligned.m8n8.x4.shared.b16 {%0,%1,%2,%3}, [%4];"
                 : "=r"(r[0]), "=r"(r[1]), "=r"(r[2]), "=r"(r[3]) : "r"(a));
}
__device__ __forceinline__ void ldsm4t(uint32_t* r, uint32_t a) {
    asm volatile("ldmatrix.sync.aligned.m8n8.x4.trans.shared.b16 {%0,%1,%2,%3}, [%4];"
                 : "=r"(r[0]), "=r"(r[1]), "=r"(r[2]), "=r"(r[3]) : "r"(a));
}
__device__ __forceinline__ void cp16(uint32_t d, const void* s) {
    asm volatile("cp.async.cg.shared.global [%0], [%1], 16;" :: "r"(d), "l"(s));
}
#define CP_COMMIT() asm volatile("cp.async.commit_group;" ::: "memory")
#define CP_WAIT(n)  asm volatile("cp.async.wait_group %0;" :: "n"(n) : "memory")

// bf16 [rows x 32] K-slab (src already at k-offset) -> col-half `st` of swizzled tile.
__device__ __forceinline__ void cpa(const __nv_bfloat16* __restrict__ s, int ld, uint32_t db,
                                    int st, int tid) {
    for (int i = tid; i < 512; i += 256) {
        const int r = i >> 2, q = i & 3, c = st * 4 + q;
        cp16(db + r * 128 + ((c ^ (r & 7)) << 4), s + (size_t)r * ld + q * 8);
    }
}
// bf16 [32 x 64] n-rows slab (av B): rows are 128B; stage occupies row range.
__device__ __forceinline__ void cpb(const __nv_bfloat16* __restrict__ s, uint32_t db,
                                    int st, int tid) {
    if (tid < 256) {
        const int r = tid >> 3, q = tid & 7, pr = st * 32 + r;
        cp16(db + pr * 128 + ((q ^ (pr & 7)) << 4), s + (size_t)r * DKH + q * 8);
    }
}

// One K=32 stage, fragment-reuse: Ah/Al loaded once per k16, B streamed.
template<int NB, bool TRB>
__device__ __forceinline__ void stage_mma(uint32_t sb, int s, int wid, int lane, float* acc) {
    constexpr int NA = NB / 16;
    const int wm = (wid >> 1) * 32, wn = (wid & 1) * (NB / 2);
    const int l15 = lane & 15, lh = lane >> 4;
    #pragma unroll
    for (int kk = 0; kk < 2; ++kk) {
        uint32_t ah[2][4], al[2][4];
        const int ca = s * 4 + kk * 2 + lh;
        #pragma unroll
        for (int im = 0; im < 2; ++im) {
            const int r = wm + im * 16 + l15;
            const uint32_t sw = r * 128 + ((ca ^ (r & 7)) << 4);
            ldsm4(ah[im], sb + OF_AH + sw);
            ldsm4(al[im], sb + OF_AL + sw);
        }
        #pragma unroll
        for (int ap = 0; ap < NA / 2; ++ap) {
            uint32_t bh[4], bl[4];
            if (!TRB) {
                const int r = wn + ap * 16 + l15;
                const uint32_t sw = r * 128 + ((ca ^ (r & 7)) << 4);
                ldsm4(bh, sb + OF_BH + sw);
                ldsm4(bl, sb + OF_BL + sw);
                #pragma unroll
                for (int im = 0; im < 2; ++im) {
                    float* d0 = acc + (im * NA + ap * 2) * 4;
                    float* d1 = acc + (im * NA + ap * 2 + 1) * 4;
                    mma16816(d0, ah[im], bh[0], bh[2]);
                    mma16816(d1, ah[im], bh[1], bh[3]);
                    mma16816(d0, ah[im], bl[0], bl[2]);
                    mma16816(d1, ah[im], bl[1], bl[3]);
                    mma16816(d0, al[im], bh[0], bh[2]);
                    mma16816(d1, al[im], bh[1], bh[3]);
                }
            } else {
                const int r = s * 32 + kk * 16 + l15, c = ((wn + ap * 16) >> 3) + lh;
                const uint32_t sw = r * 128 + ((c ^ (r & 7)) << 4);
                ldsm4t(bh, sb + OF_BH + sw);
                ldsm4t(bl, sb + OF_BL + sw);
                #pragma unroll
                for (int im = 0; im < 2; ++im) {
                    float* d0 = acc + (im * NA + ap * 2) * 4;
                    float* d1 = acc + (im * NA + ap * 2 + 1) * 4;
                    mma16816(d0, ah[im], bh[0], bh[1]);
                    mma16816(d1, ah[im], bh[2], bh[3]);
                    mma16816(d0, ah[im], bl[0], bl[1]);
                    mma16816(d1, ah[im], bl[2], bl[3]);
                    mma16816(d0, al[im], bh[0], bh[1]);
                    mma16816(d1, al[im], bh[2], bh[3]);
                }
            }
        }
    }
}

__global__ void detect_mask_kernel(const unsigned int* __restrict__ m) {
    __shared__ int s01, sf;
    if (threadIdx.x == 0) { s01 = 1; sf = 1; }
    __syncthreads();
    int a01 = 1, af = 1;
    for (int i = threadIdx.x; i < 65536; i += blockDim.x) {
        const unsigned int w = m[i];
        if (w > 1u) a01 = 0;
        if (w != 0u && w != 0x3f800000u) af = 0;
    }
    if (!a01) atomicAnd(&s01, 0);
    if (!af)  atomicAnd(&sf, 0);
    __syncthreads();
    if (threadIdx.x == 0) g_mask_mode = s01 ? 1 : (sf ? 2 : 0);
}

__global__ __launch_bounds__(256) void convert_in_kernel(
    const float* __restrict__ Q, const float* __restrict__ K, const float* __restrict__ V) {
    const int z = blockIdx.z;
    const float* s = (z == 0) ? Q : (z == 1) ? K : V;
    const size_t i = ((size_t)blockIdx.x * 256 + threadIdx.x) * 4;
    const float4 v = *(const float4*)(s + i);
    __nv_bfloat16 h0, h1, h2, h3, l0, l1, l2, l3;
    split_bf(v.x, h0, l0); split_bf(v.y, h1, l1); split_bf(v.z, h2, l2); split_bf(v.w, h3, l3);
    const size_t o = (size_t)z * QKV_ELEMS + i;
    *(uint2*)(g_inh + o) = make_uint2(pack2(h0, h1), pack2(h2, h3));
    *(uint2*)(g_inl + o) = make_uint2(pack2(l0, l1), pack2(l2, l3));
}

__global__ __launch_bounds__(256) void convert_w_kernel(
    const float* __restrict__ WQ, const float* __restrict__ WK,
    const float* __restrict__ WV, const float* __restrict__ Wfc) {
    const int z = blockIdx.z;
    const float* W = (z == 0) ? WQ : (z == 1) ? WK : (z == 2) ? WV : Wfc;
    __shared__ float t[32][33];
    const int tx = threadIdx.x & 31, ty = threadIdx.x >> 5;
    const int x0 = blockIdx.x * 32, y0 = blockIdx.y * 32;
    #pragma unroll
    for (int j = 0; j < 4; ++j)
        t[ty + j * 8][tx] = W[(size_t)(y0 + ty + j * 8) * EMBD + x0 + tx];
    __syncthreads();
    __nv_bfloat16* dh = g_wth + (size_t)z * EMBD * EMBD;
    __nv_bfloat16* dl = g_wtl + (size_t)z * EMBD * EMBD;
    #pragma unroll
    for (int j = 0; j < 4; ++j) {
        __nv_bfloat16 hh, ll;
        split_bf(t[tx][ty + j * 8], hh, ll);
        const size_t o = (size_t)(x0 + ty + j * 8) * EMBD + y0 + tx;
        dh[o] = hh; dl[o] = ll;
    }
}

// QKV projection: 128x128 tiles, 32 pipelined K=32 stages.
__global__ __launch_bounds__(256, 2) void proj_gemm(void) {
    extern __shared__ unsigned char smem[];
    const uint32_t sb = smem_u32(smem);
    const int tid = threadIdx.x, wid = tid >> 5, lane = tid & 31;
    const int z = blockIdx.z, m0 = blockIdx.y * 128, n0 = blockIdx.x * 128;
    const __nv_bfloat16* Ah = g_inh + (size_t)z * QKV_ELEMS + (size_t)m0 * EMBD;
    const __nv_bfloat16* Al = g_inl + (size_t)z * QKV_ELEMS + (size_t)m0 * EMBD;
    const __nv_bfloat16* Bh = g_wth + (size_t)z * EMBD * EMBD + (size_t)n0 * EMBD;
    const __nv_bfloat16* Bl = g_wtl + (size_t)z * EMBD * EMBD + (size_t)n0 * EMBD;
    float acc[64] = {};
    cpa(Ah, EMBD, sb + OF_AH, 0, tid); cpa(Al, EMBD, sb + OF_AL, 0, tid);
    cpa(Bh, EMBD, sb + OF_BH, 0, tid); cpa(Bl, EMBD, sb + OF_BL, 0, tid);
    CP_COMMIT();
    for (int c = 0; c < 32; ++c) {
        if (c < 31) {
            const int k = (c + 1) * 32, s = (c + 1) & 1;
            cpa(Ah + k, EMBD, sb + OF_AH, s, tid); cpa(Al + k, EMBD, sb + OF_AL, s, tid);
            cpa(Bh + k, EMBD, sb + OF_BH, s, tid); cpa(Bl + k, EMBD, sb + OF_BL, s, tid);
            CP_COMMIT(); CP_WAIT(1);
        } else CP_WAIT(0);
        __syncthreads();
        stage_mma<128, false>(sb, c & 1, wid, lane, acc);
        __syncthreads();
    }
    const int gid = lane >> 2, t4 = lane & 3, wm = (wid >> 1) * 32, wn = (wid & 1) * 64;
    __nv_bfloat16* dh = (z == 0) ? g_qh : (z == 1) ? g_kh : g_vh;
    __nv_bfloat16* dl = (z == 0) ? g_ql : (z == 1) ? g_kl : g_vl;
    #pragma unroll
    for (int im = 0; im < 2; ++im)
        #pragma unroll
        for (int ia = 0; ia < 8; ++ia) {
            const float* cc = acc + (im * 8 + ia) * 4;
            const int n = n0 + wn + ia * 8 + t4 * 2, h = n >> 6, d = n & 63;
            #pragma unroll
            for (int hr = 0; hr < 2; ++hr) {
                const int m = m0 + wm + im * 16 + gid + hr * 8;
                const int b = m >> 11, s = m & (SEQ - 1);
                __nv_bfloat16 p0, p1, q0, q1;
                split_bf(cc[hr * 2 + 0], p0, q0);
                split_bf(cc[hr * 2 + 1], p1, q1);
                const size_t o = (((size_t)(b * NH + h)) * SEQ + s) * DKH + d;
                *(uint32_t*)(dh + o) = pack2(p0, p1);
                *(uint32_t*)(dl + o) = pack2(q0, q1);
            }
        }
}

// scores: per (b,h) 128x128 tile, 2 stages (K=64 total), masked raw scores out.
__global__ __launch_bounds__(256, 2) void scores_gemm(
    const void* __restrict__ mask, float* __restrict__ attn) {
    extern __shared__ unsigned char smem[];
    const uint32_t sb = smem_u32(smem);
    const int tid = threadIdx.x, wid = tid >> 5, lane = tid & 31;
    const int z = blockIdx.z, b = z >> 4;
    const int m0 = blockIdx.y * 128, n0 = blockIdx.x * 128;
    const size_t zo = (size_t)z * SEQ * DKH;
    const __nv_bfloat16* qh = g_qh + zo + (size_t)m0 * DKH;
    const __nv_bfloat16* ql = g_ql + zo + (size_t)m0 * DKH;
    const __nv_bfloat16* kh = g_kh + zo + (size_t)n0 * DKH;
    const __nv_bfloat16* kl = g_kl + zo + (size_t)n0 * DKH;
    #pragma unroll
    for (int s = 0; s < 2; ++s) {
        cpa(qh + s * 32, DKH, sb + OF_AH, s, tid); cpa(ql + s * 32, DKH, sb + OF_AL, s, tid);
        cpa(kh + s * 32, DKH, sb + OF_BH, s, tid); cpa(kl + s * 32, DKH, sb + OF_BL, s, tid);
    }
    CP_COMMIT(); CP_WAIT(0);
    __syncthreads();
    float acc[64] = {};
    stage_mma<128, false>(sb, 0, wid, lane, acc);
    stage_mma<128, false>(sb, 1, wid, lane, acc);
    __syncthreads();
    {
        const int mode = g_mask_mode;
        for (int i = tid; i < 128 * 32; i += 256) {
            const int r = i >> 5, c0 = (i & 31) * 4;
            const size_t g = ((size_t)b * SEQ + m0 + r) * SEQ + n0 + c0;
            uint32_t f4;
            if (mode == 1) {
                const int4 w = *(const int4*)((const int*)mask + g);
                f4 = (w.x?1u:0u) | ((w.y?1u:0u)<<8) | ((w.z?1u:0u)<<16) | ((w.w?1u:0u)<<24);
            } else if (mode == 2) {
                const float4 w = *(const float4*)((const float*)mask + g);
                f4 = (w.x!=0.f?1u:0u) | ((w.y!=0.f?1u:0u)<<8) | ((w.z!=0.f?1u:0u)<<16) | ((w.w!=0.f?1u:0u)<<24);
            } else {
                f4 = *(const uint32_t*)((const unsigned char*)mask + g);
            }
            *(uint32_t*)(smem + OF_AH + r * 132 + c0) = f4;
        }
    }
    __syncthreads();
    const int gid = lane >> 2, t4 = lane & 3, wm = (wid >> 1) * 32, wn = (wid & 1) * 64;
    #pragma unroll
    for (int im = 0; im < 2; ++im)
        #pragma unroll
        for (int ia = 0; ia < 8; ++ia) {
            const float* cc = acc + (im * 8 + ia) * 4;
            const int ln = wn + ia * 8 + t4 * 2;
            #pragma unroll
            for (int hr = 0; hr < 2; ++hr) {
                const int rl = wm + im * 16 + gid + hr * 8;
                const unsigned char* fr = smem + OF_AH + rl * 132 + ln;
                float2 o;
                o.x = fr[0] ? -1e9f : cc[hr * 2 + 0] * 0.125f;
                o.y = fr[1] ? -1e9f : cc[hr * 2 + 1] * 0.125f;
                *(float2*)(attn + ((size_t)z * SEQ + m0 + rl) * SEQ + n0 + ln) = o;
            }
        }
}

__global__ __launch_bounds__(256) void rowstats_kernel(const float* __restrict__ attn) {
    const float* p = attn + (size_t)blockIdx.x * SEQ;
    const int t = threadIdx.x;
    float v[8], m = -3.4e38f;
    #pragma unroll
    for (int j = 0; j < 8; ++j) { v[j] = p[t + j * 256]; m = fmaxf(m, v[j]); }
    __shared__ float red[8]; __shared__ float bmax;
    #pragma unroll
    for (int o = 16; o > 0; o >>= 1) m = fmaxf(m, __shfl_xor_sync(0xffffffffu, m, o));
    if ((t & 31) == 0) red[t >> 5] = m;
    __syncthreads();
    if (t == 0) {
        float mm = red[0];
        #pragma unroll
        for (int i = 1; i < 8; ++i) mm = fmaxf(mm, red[i]);
        bmax = mm;
    }
    __syncthreads();
    m = bmax;
    float s = 0.f;
    #pragma unroll
    for (int j = 0; j < 8; ++j) s += __expf(v[j] - m);
    __syncthreads();
    #pragma unroll
    for (int o = 16; o > 0; o >>= 1) s += __shfl_xor_sync(0xffffffffu, s, o);
    if ((t & 31) == 0) red[t >> 5] = s;
    __syncthreads();
    if (t == 0) {
        float ss = red[0];
        #pragma unroll
        for (int i = 1; i < 8; ++i) ss += red[i];
        g_rstat[blockIdx.x] = make_float2(m, 1.0f / ss);
    }
}

__global__ __launch_bounds__(256) void softmax_kernel(float* __restrict__ attn) {
    float* p = attn + (size_t)blockIdx.x * SEQ;
    const int t = threadIdx.x;
    float v[8], m = -3.4e38f;
    #pragma unroll
    for (int j = 0; j < 8; ++j) { v[j] = p[t + j * 256]; m = fmaxf(m, v[j]); }
    __shared__ float red[8]; __shared__ float bmax, bsum;
    #pragma unroll
    for (int o = 16; o > 0; o >>= 1) m = fmaxf(m, __shfl_xor_sync(0xffffffffu, m, o));
    if ((t & 31) == 0) red[t >> 5] = m;
    __syncthreads();
    if (t == 0) {
        float mm = red[0];
        #pragma unroll
        for (int i = 1; i < 8; ++i) mm = fmaxf(mm, red[i]);
        bmax = mm;
    }
    __syncthreads();
    m = bmax;
    float s = 0.f;
    #pragma unroll
    for (int j = 0; j < 8; ++j) { v[j] = __expf(v[j] - m); s += v[j]; }
    __syncthreads();
    #pragma unroll
    for (int o = 16; o > 0; o >>= 1) s += __shfl_xor_sync(0xffffffffu, s, o);
    if ((t & 31) == 0) red[t >> 5] = s;
    __syncthreads();
    if (t == 0) {
        float ss = red[0];
        #pragma unroll
        for (int i = 1; i < 8; ++i) ss += red[i];
        bsum = ss;
    }
    __syncthreads();
    const float inv = 1.0f / bsum;
    #pragma unroll
    for (int j = 0; j < 8; ++j) p[t + j * 256] = v[j] * inv;
}

// av: per (b,h) M=2048 N=64 K=2048; 64 pipelined K=32 stages.
// A: f32 register prefetch (+fused softmax) -> split STS; B: cp.async.
__global__ __launch_bounds__(256, 2) void av_gemm(const float* __restrict__ attn, int fused) {
    extern __shared__ unsigned char smem[];
    const uint32_t sb = smem_u32(smem);
    const int tid = threadIdx.x, wid = tid >> 5, lane = tid & 31;
    const int z = blockIdx.z, b = z >> 4, h = z & 15, m0 = blockIdx.y * 128;
    const size_t zo = (size_t)z * SEQ * DKH;
    const float* Ab = attn + ((size_t)z * SEQ + m0) * SEQ;
    float2* st = (float2*)smem;
    if (fused && tid < 128) st[tid] = g_rstat[(size_t)z * SEQ + m0 + tid];
    const int pr0 = (tid + 0 * 256) >> 3, pq0 = tid & 7;
    float4 pa[4];
    #pragma unroll
    for (int j = 0; j < 4; ++j) {
        const int i = tid + j * 256;
        pa[j] = *(const float4*)(Ab + (size_t)(i >> 3) * SEQ + (i & 7) * 4);
    }
    cpb(g_vh + zo, sb + OF_BH, 0, tid);
    cpb(g_vl + zo, sb + OF_BL, 0, tid);
    CP_COMMIT();
    __syncthreads();           // st[] visible
    float acc[32] = {};
    for (int c = 0; c < 64; ++c) {
        const int s = c & 1;
        #pragma unroll
        for (int j = 0; j < 4; ++j) {
            const int i = tid + j * 256, r = i >> 3, q = i & 7;
            float4 v = pa[j];
            if (fused) {
                const float2 w = st[r];
                v.x = __expf(v.x - w.x) * w.y; v.y = __expf(v.y - w.x) * w.y;
                v.z = __expf(v.z - w.x) * w.y; v.w = __expf(v.w - w.x) * w.y;
            }
            __nv_bfloat16 h0, h1, h2, h3, l0, l1, l2, l3;
            split_bf(v.x, h0, l0); split_bf(v.y, h1, l1);
            split_bf(v.z, h2, l2); split_bf(v.w, h3, l3);
            const int cch = s * 4 + (q >> 1);
            const uint32_t ad = r * 128 + ((cch ^ (r & 7)) << 4) + (q & 1) * 8;
            *(uint2*)(smem + OF_AH + ad) = make_uint2(pack2(h0, h1), pack2(h2, h3));
            *(uint2*)(smem + OF_AL + ad) = make_uint2(pack2(l0, l1), pack2(l2, l3));
        }
        if (c < 63) {
            const int k = (c + 1) * 32, sn = (c + 1) & 1;
            #pragma unroll
            for (int j = 0; j < 4; ++j) {
                const int i = tid + j * 256;
                pa[j] = *(const float4*)(Ab + (size_t)(i >> 3) * SEQ + k + (i & 7) * 4);
            }
            cpb(g_vh + zo + (size_t)k * DKH, sb + OF_BH, sn, tid);
            cpb(g_vl + zo + (size_t)k * DKH, sb + OF_BL, sn, tid);
            CP_COMMIT(); CP_WAIT(1);
        } else CP_WAIT(0);
        __syncthreads();
        stage_mma<64, true>(sb, s, wid, lane, acc);
        __syncthreads();
    }
    (void)pr0; (void)pq0;
    const int gid = lane >> 2, t4 = lane & 3, wm = (wid >> 1) * 32, wn = (wid & 1) * 32;
    #pragma unroll
    for (int im = 0; im < 2; ++im)
        #pragma unroll
        for (int ia = 0; ia < 4; ++ia) {
            const float* cc = acc + (im * 4 + ia) * 4;
            const int d = wn + ia * 8 + t4 * 2;
            #pragma unroll
            for (int hr = 0; hr < 2; ++hr) {
                const int m = m0 + wm + im * 16 + gid + hr * 8;
                __nv_bfloat16 p0, p1, q0, q1;
                split_bf(cc[hr * 2 + 0], p0, q0);
                split_bf(cc[hr * 2 + 1], p1, q1);
                const size_t o = ((size_t)(b * SEQ + m)) * EMBD + h * 64 + d;
                *(uint32_t*)(g_ph + o) = pack2(p0, p1);
                *(uint32_t*)(g_pl + o) = pack2(q0, q1);
            }
        }
}

// fc: out = pred @ Wfc, 128x128 tiles, 32 pipelined stages, f32 output.
__global__ __launch_bounds__(256, 2) void fc_gemm(float* __restrict__ out) {
    extern __shared__ unsigned char smem[];
    const uint32_t sb = smem_u32(smem);
    const int tid = threadIdx.x, wid = tid >> 5, lane = tid & 31;
    const int m0 = blockIdx.y * 128, n0 = blockIdx.x * 128;
    const __nv_bfloat16* Ah = g_ph + (size_t)m0 * EMBD;
    const __nv_bfloat16* Al = g_pl + (size_t)m0 * EMBD;
    const __nv_bfloat16* Bh = g_wth + (size_t)3 * EMBD * EMBD + (size_t)n0 * EMBD;
    const __nv_bfloat16* Bl = g_wtl + (size_t)3 * EMBD * EMBD + (size_t)n0 * EMBD;
    float acc[64] = {};
    cpa(Ah, EMBD, sb + OF_AH, 0, tid); cpa(Al, EMBD, sb + OF_AL, 0, tid);
    cpa(Bh, EMBD, sb + OF_BH, 0, tid); cpa(Bl, EMBD, sb + OF_BL, 0, tid);
    CP_COMMIT();
    for (int c = 0; c < 32; ++c) {
        if (c < 31) {
            const int k = (c + 1) * 32, s = (c + 1) & 1;
            cpa(Ah + k, EMBD, sb + OF_AH, s, tid); cpa(Al + k, EMBD, sb + OF_AL, s, tid);
            cpa(Bh + k, EMBD, sb + OF_BH, s, tid); cpa(Bl + k, EMBD, sb + OF_BL, s, tid);
            CP_COMMIT(); CP_WAIT(1);
        } else CP_WAIT(0);
        __syncthreads();
        stage_mma<128, false>(sb, c & 1, wid, lane, acc);
        __syncthreads();
    }
    const int gid = lane >> 2, t4 = lane & 3, wm = (wid >> 1) * 32, wn = (wid & 1) * 64;
    #pragma unroll
    for (int im = 0; im < 2; ++im)
        #pragma unroll
        for (int ia = 0; ia < 8; ++ia) {
            const float* cc = acc + (im * 8 + ia) * 4;
            const int n = n0 + wn + ia * 8 + t4 * 2;
            #pragma unroll
            for (int hr = 0; hr < 2; ++hr) {
                const int m = m0 + wm + im * 16 + gid + hr * 8;
                *(float2*)(out + (size_t)m * EMBD + n) =
                    make_float2(cc[hr * 2 + 0], cc[hr * 2 + 1]);
            }
        }
}

extern "C" void kernel_launch(void* const* d_in, const int* in_sizes, int n_in,
                              void* d_out, int out_size) {
    const float* Q = (const float*)d_in[0];
    const float* K = (const float*)d_in[1];
    const float* V = (const float*)d_in[2];
    const void* mask = d_in[3];
    const float* WQ = (const float*)d_in[4];
    const float* WK = (const float*)d_in[5];
    const float* WV = (const float*)d_in[6];
    const float* Wfc = (const float*)d_in[7];
    float* out = (float*)d_out;

    const int attn_out = (out_size >= (int)(PRED_ELEMS + ATTN_ELEMS));
    float* attn_ptr;
    if (attn_out) {
        attn_ptr = out + PRED_ELEMS;
    } else {
        void* p = nullptr;
        cudaGetSymbolAddress(&p, g_attn_fb);
        attn_ptr = (float*)p;
    }

    cudaFuncSetAttribute(proj_gemm,   cudaFuncAttributeMaxDynamicSharedMemorySize, SMEM_BYTES);
    cudaFuncSetAttribute(scores_gemm, cudaFuncAttributeMaxDynamicSharedMemorySize, SMEM_BYTES);
    cudaFuncSetAttribute(av_gemm,     cudaFuncAttributeMaxDynamicSharedMemorySize, SMEM_BYTES);
    cudaFuncSetAttribute(fc_gemm,     cudaFuncAttributeMaxDynamicSharedMemorySize, SMEM_BYTES);

    detect_mask_kernel<<<1, 1024>>>((const unsigned int*)mask);
    convert_in_kernel<<<dim3(QKV_ELEMS / 1024, 1, 3), 256>>>(Q, K, V);
    convert_w_kernel<<<dim3(32, 32, 4), 256>>>(WQ, WK, WV, Wfc);
    proj_gemm<<<dim3(8, 64, 3), 256, SMEM_BYTES>>>();
    scores_gemm<<<dim3(16, 16, BH), 256, SMEM_BYTES>>>(mask, attn_ptr);
    if (attn_out) {
        softmax_kernel<<<BH * SEQ, 256>>>(attn_ptr);
        av_gemm<<<dim3(1, 16, BH), 256, SMEM_BYTES>>>(attn_ptr, 0);
    } else {
        rowstats_kernel<<<BH * SEQ, 256>>>(attn_ptr);
        av_gemm<<<dim3(1, 16, BH), 256, SMEM_BYTES>>>(attn_ptr, 1);
    }
    fc_gemm<<<dim3(8, 64, 1), 256, SMEM_BYTES>>>(out);
}